// round 15
// baseline (speedup 1.0000x reference)
#include <cuda_runtime.h>
#include <cstdint>

#define B_ 4
#define C_ 64
#define N_ 8192
#define K_ 16
#define OUT_ 128
#define TILE_N 64
#define H_STRIDE 68   // padded row stride for H in smem (floats), mult of 4 for float4

// Scratch (no cudaMalloc allowed): transposed x [b][n][c] and permuted-transposed W [row][o]
__device__ float g_xT[B_ * N_ * C_];          // 8 MB
__device__ float g_WT[OUT_ * 2 * C_];         // 64 KB

// ---------------------------------------------------------------------------
// Transpose x (B,C,N) -> xT (B,N,C), classic 32x32 smem tile
// ---------------------------------------------------------------------------
__global__ void transpose_x_kernel(const float* __restrict__ x) {
    __shared__ float t[32][33];
    const int b  = blockIdx.z;
    const int c0 = blockIdx.y * 32;
    const int n0 = blockIdx.x * 32;
    const int tx = threadIdx.x, ty = threadIdx.y;
#pragma unroll
    for (int i = 0; i < 32; i += 8)
        t[ty + i][tx] = x[((b * C_) + (c0 + ty + i)) * N_ + n0 + tx];
    __syncthreads();
#pragma unroll
    for (int i = 0; i < 32; i += 8)
        g_xT[(b * N_ + (n0 + ty + i)) * C_ + c0 + tx] = t[tx][ty + i];
}

// ---------------------------------------------------------------------------
// Transpose + permute W (128 x 128) -> g_WT[row][o], where the reference's
// interleaved h layout h[2c]=x_c, h[2c+1]=e_c is mapped to
// row(c2) = c2/2 (even c2, the x part) or 64 + c2/2 (odd c2, the e part).
// ---------------------------------------------------------------------------
__global__ void transpose_w_kernel(const float* __restrict__ W) {
    __shared__ float t[32][33];
    const int c0 = blockIdx.y * 32;
    const int o0 = blockIdx.x * 32;
    const int tx = threadIdx.x, ty = threadIdx.y;
#pragma unroll
    for (int i = 0; i < 32; i += 8)
        t[ty + i][tx] = W[(o0 + ty + i) * (2 * C_) + c0 + tx];
    __syncthreads();
#pragma unroll
    for (int i = 0; i < 32; i += 8) {
        const int c   = c0 + ty + i;                       // original h-channel index
        const int row = (c & 1) ? (C_ + (c >> 1)) : (c >> 1);
        g_WT[row * OUT_ + o0 + tx] = t[tx][ty + i];        // coalesced in o
    }
}

// ---------------------------------------------------------------------------
// Fused gather/max + 128x64x128 GEMM per tile of 64 nodes.
//  - 8 warps; each warp gathers 8 nodes (lane covers channels {2l, 2l+1} via
//    float2 -> fully coalesced 256B row reads from L2-resident xT).
//  - H staged in smem as [row][H_STRIDE] (x rows 0..63, e rows 64..127).
//  - GEMM thread tile: 8 outputs x 4 nodes using packed fma.rn.f32x2 over
//    o-pairs (pairs come directly from the float4 W_s load).
// ---------------------------------------------------------------------------
__global__ __launch_bounds__(256, 2)
void mrconv_main(const int* __restrict__ edge,
                 const float* __restrict__ bias,
                 float* __restrict__ out) {
    extern __shared__ float smem[];
    float* W_s = smem;                            // 128*128 floats (64 KB)
    float* H_s = smem + OUT_ * 128;               // 128*H_STRIDE floats
    float* b_s = H_s + 128 * H_STRIDE;            // 128 floats

    const int tid    = threadIdx.x;
    const int b      = blockIdx.x >> 7;           // 128 tiles per batch
    const int n_base = (blockIdx.x & 127) * TILE_N;

    // Stage W (already permuted/transposed) and bias — coalesced, conflict-free
    {
        const float4* src = (const float4*)g_WT;
        float4*       dst = (float4*)W_s;
#pragma unroll
        for (int i = tid; i < OUT_ * 32; i += 256) dst[i] = src[i];
        if (tid < OUT_) b_s[tid] = bias[tid];
    }

    // ---- gather + running max over K neighbors ----
    {
        const int w = tid >> 5, lane = tid & 31;
        const float2* xTb = (const float2*)g_xT + b * (N_ * C_ / 2);
        const int* ej = edge + (b * N_) * K_;                // edge_index[0] = j
        const int* ei = edge + (B_ * N_ + b * N_) * K_;      // edge_index[1] = i
        for (int r = 0; r < 8; ++r) {
            const int nl = w * 8 + r;
            const int n  = n_base + nl;
            // lanes 0..15 hold j_k, lanes 16..31 hold i_k
            const int v = (lane < 16) ? ej[n * K_ + lane] : ei[n * K_ + (lane - 16)];
            float mx = -3.0e38f, my = -3.0e38f;
#pragma unroll
            for (int k = 0; k < 16; ++k) {
                const int jx = __shfl_sync(0xffffffffu, v, k);
                const int ix = __shfl_sync(0xffffffffu, v, k + 16);
                const float2 aj = xTb[jx * 32 + lane];
                const float2 ai = xTb[ix * 32 + lane];
                mx = fmaxf(mx, aj.x - ai.x);
                my = fmaxf(my, aj.y - ai.y);
            }
            const float2 xv = xTb[n * 32 + lane];
            H_s[(2 * lane) * H_STRIDE + nl]            = xv.x;  // x channel 2l   -> row 2l
            H_s[(2 * lane + 1) * H_STRIDE + nl]        = xv.y;  // x channel 2l+1 -> row 2l+1
            H_s[(C_ + 2 * lane) * H_STRIDE + nl]       = mx;    // e channel 2l   -> row 64+2l
            H_s[(C_ + 2 * lane + 1) * H_STRIDE + nl]   = my;    // e channel 2l+1 -> row 64+2l+1
        }
    }
    __syncthreads();

    // ---- GEMM: out[o][n] = sum_row W_s[row][o] * H_s[row][n] ----
    const int ng = tid & 15;     // n-group: nodes ng*4 .. ng*4+3
    const int og = tid >> 4;     // o-group: outputs og*8 .. og*8+7

    unsigned long long acc[4][4];   // [o-pair][n], packed f32x2 (lo=even o, hi=odd o)
#pragma unroll
    for (int p = 0; p < 4; ++p)
#pragma unroll
        for (int i = 0; i < 4; ++i) acc[p][i] = 0ull;

    const float4* W4 = (const float4*)W_s;
    const float4* H4 = (const float4*)H_s;
#pragma unroll 8
    for (int c = 0; c < 128; ++c) {
        const float4 wA = W4[c * 32 + og * 2];          // outputs og*8 + 0..3
        const float4 wB = W4[c * 32 + og * 2 + 1];      // outputs og*8 + 4..7
        const float4 h  = H4[c * (H_STRIDE / 4) + ng];  // nodes ng*4 + 0..3
        unsigned long long wp[4], hp[4];
        asm("mov.b64 %0, {%1, %2};" : "=l"(wp[0]) : "f"(wA.x), "f"(wA.y));
        asm("mov.b64 %0, {%1, %2};" : "=l"(wp[1]) : "f"(wA.z), "f"(wA.w));
        asm("mov.b64 %0, {%1, %2};" : "=l"(wp[2]) : "f"(wB.x), "f"(wB.y));
        asm("mov.b64 %0, {%1, %2};" : "=l"(wp[3]) : "f"(wB.z), "f"(wB.w));
        asm("mov.b64 %0, {%1, %1};" : "=l"(hp[0]) : "f"(h.x));
        asm("mov.b64 %0, {%1, %1};" : "=l"(hp[1]) : "f"(h.y));
        asm("mov.b64 %0, {%1, %1};" : "=l"(hp[2]) : "f"(h.z));
        asm("mov.b64 %0, {%1, %1};" : "=l"(hp[3]) : "f"(h.w));
#pragma unroll
        for (int p = 0; p < 4; ++p)
#pragma unroll
            for (int i = 0; i < 4; ++i)
                asm("fma.rn.f32x2 %0, %1, %2, %0;"
                    : "+l"(acc[p][i]) : "l"(wp[p]), "l"(hp[i]));
    }

    // ---- epilogue: bias + relu, write out[b][o][n] as float4 rows ----
    float* outB = out + (b * OUT_) * (size_t)N_;
#pragma unroll
    for (int p = 0; p < 4; ++p) {
        float lo[4], hi[4];
#pragma unroll
        for (int i = 0; i < 4; ++i)
            asm("mov.b64 {%0, %1}, %2;" : "=f"(lo[i]), "=f"(hi[i]) : "l"(acc[p][i]));
        const int oe = og * 8 + 2 * p;
        const float be = b_s[oe], bo = b_s[oe + 1];
        float4 re, ro;
        re.x = fmaxf(lo[0] + be, 0.f); re.y = fmaxf(lo[1] + be, 0.f);
        re.z = fmaxf(lo[2] + be, 0.f); re.w = fmaxf(lo[3] + be, 0.f);
        ro.x = fmaxf(hi[0] + bo, 0.f); ro.y = fmaxf(hi[1] + bo, 0.f);
        ro.z = fmaxf(hi[2] + bo, 0.f); ro.w = fmaxf(hi[3] + bo, 0.f);
        *(float4*)(outB + (size_t)oe * N_ + n_base + ng * 4)       = re;
        *(float4*)(outB + (size_t)(oe + 1) * N_ + n_base + ng * 4) = ro;
    }
}

// ---------------------------------------------------------------------------
extern "C" void kernel_launch(void* const* d_in, const int* in_sizes, int n_in,
                              void* d_out, int out_size) {
    const float* x    = (const float*)d_in[0];
    const int*   edge = (const int*)d_in[1];
    const float* W    = (const float*)d_in[2];
    const float* bias = (const float*)d_in[3];
    float*       out  = (float*)d_out;

    const dim3 tb(32, 8);
    transpose_x_kernel<<<dim3(N_ / 32, C_ / 32, B_), tb>>>(x);
    transpose_w_kernel<<<dim3(OUT_ / 32, (2 * C_) / 32, 1), tb>>>(W);

    const int smem_bytes = (OUT_ * 128 + 128 * H_STRIDE + 128) * (int)sizeof(float);
    cudaFuncSetAttribute(mrconv_main, cudaFuncAttributeMaxDynamicSharedMemorySize, smem_bytes);
    mrconv_main<<<(B_ * N_) / TILE_N, 256, smem_bytes>>>(edge, bias, out);
}